// round 2
// baseline (speedup 1.0000x reference)
#include <cuda_runtime.h>
#include <cstdint>

// Problem constants
#define NB   4
#define SEQ  2048
#define DIM  1024
#define MTOT (NB * SEQ)   // 8192

// Scratch (allocation-free rule: __device__ globals)
__device__ float g_Q[(size_t)MTOT * DIM];
__device__ float g_K[(size_t)MTOT * DIM];
__device__ float g_V[(size_t)MTOT * DIM];
__device__ float g_P[(size_t)NB * SEQ * SEQ];
__device__ float g_C[(size_t)MTOT * DIM];

__device__ __forceinline__ uint32_t f2tf32(float x) {
    uint32_t u;
    asm("cvt.rna.tf32.f32 %0, %1;" : "=r"(u) : "f"(x));
    return u;
}

__device__ __forceinline__ void mma8(float* c, const uint32_t* a, const uint32_t* b) {
    asm volatile(
        "mma.sync.aligned.m16n8k8.row.col.f32.tf32.tf32.f32 "
        "{%0,%1,%2,%3}, {%4,%5,%6,%7}, {%8,%9}, {%0,%1,%2,%3};"
        : "+f"(c[0]), "+f"(c[1]), "+f"(c[2]), "+f"(c[3])
        : "r"(a[0]), "r"(a[1]), "r"(a[2]), "r"(a[3]),
          "r"(b[0]), "r"(b[1]));
}

// C[M,N] = alpha * A[M,K] * op(B) + bias
// BT=false: B is [K,N] row-major (NN).  BT=true: B is [N,K] row-major (NT: C = A*B^T).
// All of M, N multiples of 128; K multiple of 32. blockDim = 256.
template<bool BT>
__global__ __launch_bounds__(256)
void gemm_tf32(const float* __restrict__ A, const float* __restrict__ Bm,
               const float* __restrict__ bias, float* __restrict__ C,
               int M, int N, int K, float alpha,
               size_t sA, size_t sB, size_t sC)
{
    A  += (size_t)blockIdx.z * sA;
    Bm += (size_t)blockIdx.z * sB;
    C  += (size_t)blockIdx.z * sC;

    // As: [128 m][36 k-padded]   (stride 36 -> conflict-free frag loads)
    // Bs: BT: [128 n][36 k]  |  NN: [32 k][136 n]
    __shared__ uint32_t As[128 * 36];
    __shared__ uint32_t Bs[128 * 36];   // covers max(128*36, 32*136)

    const int tid  = threadIdx.x;
    const int lane = tid & 31;
    const int warp = tid >> 5;
    const int wm   = warp & 1;   // 2 warps along M  (64 rows each)
    const int wn   = warp >> 1;  // 4 warps along N  (32 cols each)
    const int g    = lane >> 2;  // groupID 0..7
    const int tg   = lane & 3;   // thread-in-group 0..3

    const int m0 = blockIdx.y * 128;
    const int n0 = blockIdx.x * 128;

    float acc[4][4][4];
#pragma unroll
    for (int i = 0; i < 4; i++)
#pragma unroll
        for (int j = 0; j < 4; j++)
#pragma unroll
            for (int r = 0; r < 4; r++) acc[i][j][r] = 0.f;

    // A-tile loader indices: 128x32, float4 along k
    const int arow = tid >> 3;        // 0..31 (+pass*32)
    const int acol = (tid & 7) * 4;   // 0..28
    // B-tile NN loader indices: 32x128, float4 along n
    const int brow = tid >> 5;        // 0..7 (+pass*8)
    const int bcol = (lane) * 4;      // 0..124

    for (int k0 = 0; k0 < K; k0 += 32) {
        // ---- load A tile (convert to tf32 at store) ----
#pragma unroll
        for (int p = 0; p < 4; p++) {
            int r = p * 32 + arow;
            float4 v = *(const float4*)&A[(size_t)(m0 + r) * K + k0 + acol];
            uint4 t;
            t.x = f2tf32(v.x); t.y = f2tf32(v.y); t.z = f2tf32(v.z); t.w = f2tf32(v.w);
            *(uint4*)&As[r * 36 + acol] = t;
        }
        // ---- load B tile ----
        if (BT) {
#pragma unroll
            for (int p = 0; p < 4; p++) {
                int r = p * 32 + arow;   // n-row within tile
                float4 v = *(const float4*)&Bm[(size_t)(n0 + r) * K + k0 + acol];
                uint4 t;
                t.x = f2tf32(v.x); t.y = f2tf32(v.y); t.z = f2tf32(v.z); t.w = f2tf32(v.w);
                *(uint4*)&Bs[r * 36 + acol] = t;
            }
        } else {
#pragma unroll
            for (int p = 0; p < 4; p++) {
                int r = p * 8 + brow;    // k-row within tile
                float4 v = *(const float4*)&Bm[(size_t)(k0 + r) * N + n0 + bcol];
                uint4 t;
                t.x = f2tf32(v.x); t.y = f2tf32(v.y); t.z = f2tf32(v.z); t.w = f2tf32(v.w);
                *(uint4*)&Bs[r * 136 + bcol] = t;
            }
        }
        __syncthreads();

        // ---- compute: 4 k-steps of m16n8k8 ----
#pragma unroll
        for (int kk = 0; kk < 4; kk++) {
            const int kb = kk * 8;
            uint32_t a[4][4];
            uint32_t b[4][2];
#pragma unroll
            for (int mi = 0; mi < 4; mi++) {
                int mr = wm * 64 + mi * 16 + g;
                a[mi][0] = As[mr * 36 + kb + tg];
                a[mi][1] = As[(mr + 8) * 36 + kb + tg];
                a[mi][2] = As[mr * 36 + kb + tg + 4];
                a[mi][3] = As[(mr + 8) * 36 + kb + tg + 4];
            }
#pragma unroll
            for (int ni = 0; ni < 4; ni++) {
                int nr = wn * 32 + ni * 8 + g;
                if (BT) {
                    b[ni][0] = Bs[nr * 36 + kb + tg];
                    b[ni][1] = Bs[nr * 36 + kb + tg + 4];
                } else {
                    b[ni][0] = Bs[(kb + tg) * 136 + nr];
                    b[ni][1] = Bs[(kb + tg + 4) * 136 + nr];
                }
            }
#pragma unroll
            for (int mi = 0; mi < 4; mi++)
#pragma unroll
                for (int ni = 0; ni < 4; ni++)
                    mma8(acc[mi][ni], a[mi], b[ni]);
        }
        __syncthreads();
    }

    // ---- epilogue ----
#pragma unroll
    for (int mi = 0; mi < 4; mi++) {
#pragma unroll
        for (int ni = 0; ni < 4; ni++) {
            int m = m0 + wm * 64 + mi * 16;
            int n = n0 + wn * 32 + ni * 8 + 2 * tg;
            float b0 = 0.f, b1 = 0.f;
            if (bias) { b0 = bias[n]; b1 = bias[n + 1]; }
            float2 r0 = make_float2(acc[mi][ni][0] * alpha + b0,
                                    acc[mi][ni][1] * alpha + b1);
            float2 r1 = make_float2(acc[mi][ni][2] * alpha + b0,
                                    acc[mi][ni][3] * alpha + b1);
            *(float2*)&C[(size_t)(m + g) * N + n]     = r0;
            *(float2*)&C[(size_t)(m + g + 8) * N + n] = r1;
        }
    }
}

// Row softmax over 2048 columns. One block (256 threads) per row.
__global__ __launch_bounds__(256)
void softmax2048(float* __restrict__ P)
{
    float4* row = (float4*)(P + (size_t)blockIdx.x * 2048);
    const int t = threadIdx.x;

    float4 v0 = row[t];
    float4 v1 = row[256 + t];

    float mx = fmaxf(fmaxf(fmaxf(v0.x, v0.y), fmaxf(v0.z, v0.w)),
                     fmaxf(fmaxf(v1.x, v1.y), fmaxf(v1.z, v1.w)));
#pragma unroll
    for (int o = 16; o; o >>= 1) mx = fmaxf(mx, __shfl_xor_sync(0xffffffffu, mx, o));

    __shared__ float redm[8];
    __shared__ float reds[8];
    if ((t & 31) == 0) redm[t >> 5] = mx;
    __syncthreads();
    float bm = redm[0];
#pragma unroll
    for (int i = 1; i < 8; i++) bm = fmaxf(bm, redm[i]);

    v0.x = __expf(v0.x - bm); v0.y = __expf(v0.y - bm);
    v0.z = __expf(v0.z - bm); v0.w = __expf(v0.w - bm);
    v1.x = __expf(v1.x - bm); v1.y = __expf(v1.y - bm);
    v1.z = __expf(v1.z - bm); v1.w = __expf(v1.w - bm);

    float s = (v0.x + v0.y + v0.z + v0.w) + (v1.x + v1.y + v1.z + v1.w);
#pragma unroll
    for (int o = 16; o; o >>= 1) s += __shfl_xor_sync(0xffffffffu, s, o);
    if ((t & 31) == 0) reds[t >> 5] = s;
    __syncthreads();
    float bs = 0.f;
#pragma unroll
    for (int i = 0; i < 8; i++) bs += reds[i];

    float inv = 1.0f / bs;
    v0.x *= inv; v0.y *= inv; v0.z *= inv; v0.w *= inv;
    v1.x *= inv; v1.y *= inv; v1.z *= inv; v1.w *= inv;
    row[t] = v0;
    row[256 + t] = v1;
}

extern "C" void kernel_launch(void* const* d_in, const int* in_sizes, int n_in,
                              void* d_out, int out_size)
{
    const float* x  = (const float*)d_in[0];
    const float* Wq = (const float*)d_in[1];
    const float* bq = (const float*)d_in[2];
    const float* Wk = (const float*)d_in[3];
    const float* bk = (const float*)d_in[4];
    const float* Wv = (const float*)d_in[5];
    const float* bv = (const float*)d_in[6];
    const float* Wo = (const float*)d_in[7];
    const float* bo = (const float*)d_in[8];
    float* out = (float*)d_out;

    float *Q, *K, *V, *P, *C;
    cudaGetSymbolAddress((void**)&Q, g_Q);
    cudaGetSymbolAddress((void**)&K, g_K);
    cudaGetSymbolAddress((void**)&V, g_V);
    cudaGetSymbolAddress((void**)&P, g_P);
    cudaGetSymbolAddress((void**)&C, g_C);

    dim3 blk(256);
    dim3 g_proj(DIM / 128, MTOT / 128, 1);          // 8 x 64
    dim3 g_sc(SEQ / 128, SEQ / 128, NB);            // 16 x 16 x 4
    dim3 g_ctx(DIM / 128, SEQ / 128, NB);           // 8 x 16 x 4

    const float scale = 1.0f / 32.0f;               // 1/sqrt(1024)

    // QKV projections
    gemm_tf32<false><<<g_proj, blk>>>(x, Wq, bq, Q, MTOT, DIM, DIM, 1.f, 0, 0, 0);
    gemm_tf32<false><<<g_proj, blk>>>(x, Wk, bk, K, MTOT, DIM, DIM, 1.f, 0, 0, 0);
    gemm_tf32<false><<<g_proj, blk>>>(x, Wv, bv, V, MTOT, DIM, DIM, 1.f, 0, 0, 0);

    // scores = scale * Q K^T (per batch)
    gemm_tf32<true><<<g_sc, blk>>>(Q, K, nullptr, P, SEQ, SEQ, DIM, scale,
                                   (size_t)SEQ * DIM, (size_t)SEQ * DIM,
                                   (size_t)SEQ * SEQ);

    // softmax rows
    softmax2048<<<MTOT, 256>>>(P);

    // ctx = attn V (per batch)
    gemm_tf32<false><<<g_ctx, blk>>>(P, V, nullptr, C, SEQ, DIM, SEQ, 1.f,
                                     (size_t)SEQ * SEQ, (size_t)SEQ * DIM,
                                     (size_t)SEQ * DIM);

    // out = ctx Wo + bo
    gemm_tf32<false><<<g_proj, blk>>>(C, Wo, bo, out, MTOT, DIM, DIM, 1.f, 0, 0, 0);
}

// round 4
// speedup vs baseline: 1.3532x; 1.3532x over previous
#include <cuda_runtime.h>
#include <cstdint>

// Problem constants
#define NB   4
#define SEQ  2048
#define DIM  1024
#define MTOT (NB * SEQ)   // 8192

// GEMM tiling
#define BM 128
#define BN 256
#define BK 32
#define ASTAGE (BM * BK * 4)            // 16384 B
#define BSTAGE (BN * BK * 4)            // 32768 B
#define STAGEB (ASTAGE + BSTAGE)        // 49152 B
#define GEMM_SMEM (3 * STAGEB)          // 147456 B (3 stages)

// ---------------- scratch (__device__ globals; no allocation allowed) ------
__device__ float g_X [(size_t)MTOT * DIM];
__device__ float g_Q [(size_t)MTOT * DIM];
__device__ float g_K [(size_t)MTOT * DIM];
__device__ float g_V [(size_t)MTOT * DIM];
__device__ float g_Vt[(size_t)MTOT * DIM];
__device__ float g_P [(size_t)NB * SEQ * SEQ];
__device__ float g_C [(size_t)MTOT * DIM];
__device__ float g_Wt[(size_t)4 * DIM * DIM];

// ---------------- helpers ---------------------------------------------------
__device__ __forceinline__ uint32_t smem_u32(const void* p) {
    uint32_t a;
    asm("{ .reg .u64 t; cvta.to.shared.u64 t, %1; cvt.u32.u64 %0, t; }" : "=r"(a) : "l"(p));
    return a;
}

// fp32 -> tf32 round-to-nearest (fp32 bit pattern, low 13 bits zero)
__device__ __forceinline__ float tf32r(float x) {
    uint32_t u;
    asm("cvt.rna.tf32.f32 %0, %1;" : "=r"(u) : "f"(x));
    return __uint_as_float(u);
}

#define CP_ASYNC16(dst, src) \
    asm volatile("cp.async.cg.shared.global [%0], [%1], 16;" :: "r"(dst), "l"(src) : "memory")
#define CP_COMMIT() asm volatile("cp.async.commit_group;" ::: "memory")
#define CP_WAIT1()  asm volatile("cp.async.wait_group 1;" ::: "memory")

__device__ __forceinline__ void ldsm4(uint32_t* r, uint32_t addr) {
    asm volatile("ldmatrix.sync.aligned.m8n8.x4.shared.b16 {%0,%1,%2,%3}, [%4];"
                 : "=r"(r[0]), "=r"(r[1]), "=r"(r[2]), "=r"(r[3]) : "r"(addr));
}

__device__ __forceinline__ void mma8(float* c, const uint32_t* a, const uint32_t* b) {
    asm volatile(
        "mma.sync.aligned.m16n8k8.row.col.f32.tf32.tf32.f32 "
        "{%0,%1,%2,%3}, {%4,%5,%6,%7}, {%8,%9}, {%0,%1,%2,%3};"
        : "+f"(c[0]), "+f"(c[1]), "+f"(c[2]), "+f"(c[3])
        : "r"(a[0]), "r"(a[1]), "r"(a[2]), "r"(a[3]),
          "r"(b[0]), "r"(b[1]));
}

// ---------------- tcgen05-free NT GEMM (mma.sync tf32 + ldmatrix + cp.async)
// C[M,N] = alpha * A[M,K] * B[N,K]^T + bias ; optionally tf32-round outputs.
// A, B K-major. M % 128 == 0, N % 256 == 0, K % 32 == 0 (and K >= 64).
// Inputs must be tf32-pre-rounded. 256 threads, 8 warps (2 m x 4 n), warp
// tile 64x64. 3-stage cp.async pipeline, SW128-style XOR swizzle.
__global__ __launch_bounds__(256, 1)
void gemm_nt_mma(const float* __restrict__ A, const float* __restrict__ B,
                 const float* __restrict__ bias, float* __restrict__ C,
                 int N, int K, float alpha, int rndOut,
                 size_t strA, size_t strB, size_t strC)
{
    extern __shared__ char smem[];
    const uint32_t sbase = smem_u32(smem);

    A += (size_t)blockIdx.z * strA;
    B += (size_t)blockIdx.z * strB;
    C += (size_t)blockIdx.z * strC;

    const int tid  = threadIdx.x;
    const int lane = tid & 31;
    const int wid  = tid >> 5;
    const int wm   = wid & 1;          // 2 warps along M (64 rows each)
    const int wn   = wid >> 1;         // 4 warps along N (64 cols each)
    const int m0   = blockIdx.y * BM;
    const int n0   = blockIdx.x * BN;

    float acc[4][8][4];
#pragma unroll
    for (int i = 0; i < 4; i++)
#pragma unroll
        for (int j = 0; j < 8; j++)
#pragma unroll
            for (int r = 0; r < 4; r++) acc[i][j][r] = 0.f;

    // loader lane mapping: 16B chunk lc of row lr (+p*32)
    const int lr = tid >> 3;           // 0..31
    const int lc = tid & 7;            // 0..7

    // ldmatrix lane address bases
    const int arow = (lane & 7) + ((lane >> 3) & 1) * 8;   // A: tiles 0/1 rows, 2/3 k+16B
    const int acol = ((lane >> 4) & 1) * 16;
    const int brow = (lane & 7) + ((lane >> 4) & 1) * 8;   // B: tiles 0/1 k+16B, 2/3 rows+8
    const int bcol = ((lane >> 3) & 1) * 16;
    const uint32_t xmask = (uint32_t)((lane & 7) << 4);    // swizzle XOR (row&7 == lane&7)

    uint32_t abase[4], bbase[4];
#pragma unroll
    for (int mi = 0; mi < 4; mi++)
        abase[mi] = (uint32_t)((wm * 64 + mi * 16 + arow) * 128 + acol);
#pragma unroll
    for (int q = 0; q < 4; q++)
        bbase[q] = (uint32_t)((wn * 64 + q * 16 + brow) * 128 + bcol);

    // stage loader: K-slab i (BK cols) into stage s
    auto loadStage = [&](int i, int s) {
        const uint32_t baseA = sbase + (uint32_t)s * STAGEB;
        const uint32_t baseB = baseA + ASTAGE;
        const float* Ag = A + (size_t)m0 * K + (size_t)i * BK + lc * 4;
        const float* Bg = B + (size_t)n0 * K + (size_t)i * BK + lc * 4;
#pragma unroll
        for (int p = 0; p < 4; p++) {
            const int r = p * 32 + lr;
            CP_ASYNC16(baseA + (uint32_t)(r * 128 + ((lc ^ (r & 7)) * 16)),
                       Ag + (size_t)r * K);
        }
#pragma unroll
        for (int p = 0; p < 8; p++) {
            const int r = p * 32 + lr;
            CP_ASYNC16(baseB + (uint32_t)(r * 128 + ((lc ^ (r & 7)) * 16)),
                       Bg + (size_t)r * K);
        }
    };

    const int nIter = K / BK;
    loadStage(0, 0); CP_COMMIT();
    loadStage(1, 1); CP_COMMIT();

    int s = 0;
    for (int i = 0; i < nIter; i++) {
        CP_WAIT1();
        __syncthreads();

        const uint32_t aS = sbase + (uint32_t)s * STAGEB;
        const uint32_t bS = aS + ASTAGE;
#pragma unroll
        for (int kk = 0; kk < 4; kk++) {
            uint32_t a[4][4];
            uint32_t b[8][2];
#pragma unroll
            for (int mi = 0; mi < 4; mi++)
                ldsm4(a[mi], aS + ((abase[mi] + kk * 32) ^ xmask));
#pragma unroll
            for (int q = 0; q < 4; q++) {
                uint32_t r[4];
                ldsm4(r, bS + ((bbase[q] + kk * 32) ^ xmask));
                b[2 * q][0]     = r[0]; b[2 * q][1]     = r[1];
                b[2 * q + 1][0] = r[2]; b[2 * q + 1][1] = r[3];
            }
#pragma unroll
            for (int mi = 0; mi < 4; mi++)
#pragma unroll
                for (int ni = 0; ni < 8; ni++)
                    mma8(acc[mi][ni], a[mi], b[ni]);
        }

        if (i + 2 < nIter) {
            int s2 = s + 2; if (s2 >= 3) s2 -= 3;
            loadStage(i + 2, s2);
        }
        CP_COMMIT();
        s++; if (s == 3) s = 0;
    }

    // ---- epilogue ----
    const int g  = lane >> 2;
    const int tg = lane & 3;
#pragma unroll
    for (int mi = 0; mi < 4; mi++) {
        const int mrow = m0 + wm * 64 + mi * 16 + g;
#pragma unroll
        for (int ni = 0; ni < 8; ni++) {
            const int nc = n0 + wn * 64 + ni * 8 + 2 * tg;
            float b0 = 0.f, b1 = 0.f;
            if (bias) { b0 = __ldg(bias + nc); b1 = __ldg(bias + nc + 1); }
            float2 r0 = make_float2(acc[mi][ni][0] * alpha + b0,
                                    acc[mi][ni][1] * alpha + b1);
            float2 r1 = make_float2(acc[mi][ni][2] * alpha + b0,
                                    acc[mi][ni][3] * alpha + b1);
            if (rndOut) {
                r0.x = tf32r(r0.x); r0.y = tf32r(r0.y);
                r1.x = tf32r(r1.x); r1.y = tf32r(r1.y);
            }
            *(float2*)&C[(size_t)mrow * N + nc]       = r0;
            *(float2*)&C[(size_t)(mrow + 8) * N + nc] = r1;
        }
    }
}

// ---------------- aux kernels ----------------------------------------------

// tf32-round copy (prepares x for the projection GEMMs)
__global__ __launch_bounds__(256)
void round_copy4(const float4* __restrict__ in, float4* __restrict__ out, int n4)
{
    int i = blockIdx.x * 256 + threadIdx.x;
    if (i < n4) {
        float4 v = in[i];
        v.x = tf32r(v.x); v.y = tf32r(v.y); v.z = tf32r(v.z); v.w = tf32r(v.w);
        out[i] = v;
    }
}

// out[C,R] = in[R,C]^T (optionally tf32-rounded); R,C multiples of 32
__global__ __launch_bounds__(256)
void transpose32(const float* __restrict__ in, float* __restrict__ out,
                 int R, int C, int rnd, size_t sIn, size_t sOut)
{
    __shared__ float t[32][33];
    in  += (size_t)blockIdx.z * sIn;
    out += (size_t)blockIdx.z * sOut;
    const int x  = blockIdx.x * 32 + threadIdx.x;
    const int y0 = blockIdx.y * 32;
#pragma unroll
    for (int j = threadIdx.y; j < 32; j += 8) {
        float v = in[(size_t)(y0 + j) * C + x];
        if (rnd) v = tf32r(v);
        t[j][threadIdx.x] = v;
    }
    __syncthreads();
    const int ox  = y0 + threadIdx.x;
    const int oy0 = blockIdx.x * 32;
#pragma unroll
    for (int j = threadIdx.y; j < 32; j += 8)
        out[(size_t)(oy0 + j) * R + ox] = t[threadIdx.x][j];
}

// row softmax over 2048 cols; outputs tf32-rounded (consumed by ctx GEMM)
__global__ __launch_bounds__(256)
void softmax2048(float* __restrict__ P)
{
    float4* row = (float4*)(P + (size_t)blockIdx.x * 2048);
    const int t = threadIdx.x;

    float4 v0 = row[t];
    float4 v1 = row[256 + t];

    float mx = fmaxf(fmaxf(fmaxf(v0.x, v0.y), fmaxf(v0.z, v0.w)),
                     fmaxf(fmaxf(v1.x, v1.y), fmaxf(v1.z, v1.w)));
#pragma unroll
    for (int o = 16; o; o >>= 1) mx = fmaxf(mx, __shfl_xor_sync(0xffffffffu, mx, o));

    __shared__ float redm[8];
    __shared__ float reds[8];
    if ((t & 31) == 0) redm[t >> 5] = mx;
    __syncthreads();
    float bm = redm[0];
#pragma unroll
    for (int i = 1; i < 8; i++) bm = fmaxf(bm, redm[i]);

    v0.x = __expf(v0.x - bm); v0.y = __expf(v0.y - bm);
    v0.z = __expf(v0.z - bm); v0.w = __expf(v0.w - bm);
    v1.x = __expf(v1.x - bm); v1.y = __expf(v1.y - bm);
    v1.z = __expf(v1.z - bm); v1.w = __expf(v1.w - bm);

    float ssum = (v0.x + v0.y + v0.z + v0.w) + (v1.x + v1.y + v1.z + v1.w);
#pragma unroll
    for (int o = 16; o; o >>= 1) ssum += __shfl_xor_sync(0xffffffffu, ssum, o);
    if ((t & 31) == 0) reds[t >> 5] = ssum;
    __syncthreads();
    float bs = 0.f;
#pragma unroll
    for (int i = 0; i < 8; i++) bs += reds[i];

    float inv = 1.0f / bs;
    v0.x = tf32r(v0.x * inv); v0.y = tf32r(v0.y * inv);
    v0.z = tf32r(v0.z * inv); v0.w = tf32r(v0.w * inv);
    v1.x = tf32r(v1.x * inv); v1.y = tf32r(v1.y * inv);
    v1.z = tf32r(v1.z * inv); v1.w = tf32r(v1.w * inv);
    row[t] = v0;
    row[256 + t] = v1;
}

// ---------------- launch ----------------------------------------------------
extern "C" void kernel_launch(void* const* d_in, const int* in_sizes, int n_in,
                              void* d_out, int out_size)
{
    const float* x  = (const float*)d_in[0];
    const float* Wq = (const float*)d_in[1];
    const float* bq = (const float*)d_in[2];
    const float* Wk = (const float*)d_in[3];
    const float* bk = (const float*)d_in[4];
    const float* Wv = (const float*)d_in[5];
    const float* bv = (const float*)d_in[6];
    const float* Wo = (const float*)d_in[7];
    const float* bo = (const float*)d_in[8];
    float* out = (float*)d_out;

    float *X, *Q, *K, *V, *Vt, *P, *C, *Wt;
    cudaGetSymbolAddress((void**)&X,  g_X);
    cudaGetSymbolAddress((void**)&Q,  g_Q);
    cudaGetSymbolAddress((void**)&K,  g_K);
    cudaGetSymbolAddress((void**)&V,  g_V);
    cudaGetSymbolAddress((void**)&Vt, g_Vt);
    cudaGetSymbolAddress((void**)&P,  g_P);
    cudaGetSymbolAddress((void**)&C,  g_C);
    cudaGetSymbolAddress((void**)&Wt, g_Wt);

    cudaFuncSetAttribute(gemm_nt_mma, cudaFuncAttributeMaxDynamicSharedMemorySize, GEMM_SMEM);

    const float scale = 1.0f / 32.0f;   // 1/sqrt(1024)
    dim3 tb(32, 8);

    // 1) tf32-round x
    round_copy4<<<(MTOT * DIM / 4 + 255) / 256, 256>>>((const float4*)x, (float4*)X, MTOT * DIM / 4);

    // 2) transpose + round weights: Wt[i] is [N,K] K-major
    transpose32<<<dim3(DIM / 32, DIM / 32, 1), tb>>>(Wq, Wt + 0 * (size_t)DIM * DIM, DIM, DIM, 1, 0, 0);
    transpose32<<<dim3(DIM / 32, DIM / 32, 1), tb>>>(Wk, Wt + 1 * (size_t)DIM * DIM, DIM, DIM, 1, 0, 0);
    transpose32<<<dim3(DIM / 32, DIM / 32, 1), tb>>>(Wv, Wt + 2 * (size_t)DIM * DIM, DIM, DIM, 1, 0, 0);
    transpose32<<<dim3(DIM / 32, DIM / 32, 1), tb>>>(Wo, Wt + 3 * (size_t)DIM * DIM, DIM, DIM, 1, 0, 0);

    dim3 g_proj(DIM / BN, MTOT / BM, 1);     // 4 x 64
    dim3 g_sc(SEQ / BN, SEQ / BM, NB);       // 8 x 16 x 4
    dim3 g_ctx(DIM / BN, SEQ / BM, NB);      // 4 x 16 x 4

    // 3) projections (outputs tf32-rounded: consumed by later MMAs)
    gemm_nt_mma<<<g_proj, 256, GEMM_SMEM>>>(X, Wt + 0 * (size_t)DIM * DIM, bq, Q, DIM, DIM, 1.f, 1, 0, 0, 0);
    gemm_nt_mma<<<g_proj, 256, GEMM_SMEM>>>(X, Wt + 1 * (size_t)DIM * DIM, bk, K, DIM, DIM, 1.f, 1, 0, 0, 0);
    gemm_nt_mma<<<g_proj, 256, GEMM_SMEM>>>(X, Wt + 2 * (size_t)DIM * DIM, bv, V, DIM, DIM, 1.f, 1, 0, 0, 0);

    // 4) Vt[b] = V[b]^T  -> [DIM, SEQ], K-major over seq (V already tf32-rounded)
    transpose32<<<dim3(DIM / 32, SEQ / 32, NB), tb>>>(V, Vt, SEQ, DIM, 0,
                                                     (size_t)SEQ * DIM, (size_t)SEQ * DIM);

    // 5) scores = scale * Q K^T (raw fp32 out; softmax rounds)
    gemm_nt_mma<<<g_sc, 256, GEMM_SMEM>>>(Q, K, nullptr, P, SEQ, DIM, scale, 0,
                                          (size_t)SEQ * DIM, (size_t)SEQ * DIM, (size_t)SEQ * SEQ);

    // 6) softmax rows (tf32-rounds its output)
    softmax2048<<<MTOT, 256>>>(P);

    // 7) ctx = attn * V   (A=P [S,S], B=Vt [D,S], K-dim = S)
    gemm_nt_mma<<<g_ctx, 256, GEMM_SMEM>>>(P, Vt, nullptr, C, DIM, SEQ, 1.f, 1,
                                           (size_t)SEQ * SEQ, (size_t)SEQ * DIM, (size_t)SEQ * DIM);

    // 8) out = ctx * Wo + bo (final fp32, no rounding)
    gemm_nt_mma<<<g_proj, 256, GEMM_SMEM>>>(C, Wt + 3 * (size_t)DIM * DIM, bo, out, DIM, DIM, 1.f, 0, 0, 0, 0);
}

// round 8
// speedup vs baseline: 1.3878x; 1.0255x over previous
#include <cuda_runtime.h>
#include <cstdint>

// Problem constants
#define NB   4
#define SEQ  2048
#define DIM  1024
#define MTOT (NB * SEQ)   // 8192

// GEMM tiling
#define BM 128
#define BN 256
#define BK 32
#define ASTAGE (BM * BK * 4)            // 16384 B
#define BSTAGE (BN * BK * 4)            // 32768 B
#define STAGEB (ASTAGE + BSTAGE)        // 49152 B
#define GEMM_SMEM (3 * STAGEB)          // 147456 B (3 stages; also covers 256*129*4 staging)

// Epilogue modes
#define MODE_PLAIN 0   // C = alpha*A*B^T + bias (optional rnd)
#define MODE_EXP   1   // C = tf32r(exp(alpha*acc)); aux = partial row sums [rows][32]
#define MODE_NORM  2   // C = tf32r(acc * aux[row])  (aux = inv row sums)
#define MODE_TRANSV 3  // C^T write (Vt): bias + rnd, per-batch [DIM][SEQ]

// ---------------- scratch (__device__ globals; no allocation allowed) ------
__device__ float g_X [(size_t)MTOT * DIM];
__device__ float g_Q [(size_t)MTOT * DIM];
__device__ float g_K [(size_t)MTOT * DIM];
__device__ float g_Vt[(size_t)MTOT * DIM];
__device__ float g_P [(size_t)NB * SEQ * SEQ];
__device__ float g_C [(size_t)MTOT * DIM];
__device__ float g_Wt[(size_t)4 * DIM * DIM];
__device__ float g_ps[(size_t)MTOT * 32];
__device__ float g_inv[(size_t)MTOT];

// ---------------- helpers ---------------------------------------------------
__device__ __forceinline__ uint32_t smem_u32(const void* p) {
    uint32_t a;
    asm("{ .reg .u64 t; cvta.to.shared.u64 t, %1; cvt.u32.u64 %0, t; }" : "=r"(a) : "l"(p));
    return a;
}

// fp32 -> tf32 round-to-nearest (fp32 bit pattern, low 13 bits zero)
__device__ __forceinline__ float tf32r(float x) {
    uint32_t u;
    asm("cvt.rna.tf32.f32 %0, %1;" : "=r"(u) : "f"(x));
    return __uint_as_float(u);
}

#define CP_ASYNC16(dst, src) \
    asm volatile("cp.async.cg.shared.global [%0], [%1], 16;" :: "r"(dst), "l"(src) : "memory")
#define CP_COMMIT() asm volatile("cp.async.commit_group;" ::: "memory")
#define CP_WAIT1()  asm volatile("cp.async.wait_group 1;" ::: "memory")

__device__ __forceinline__ void ldsm4(uint32_t* r, uint32_t addr) {
    asm volatile("ldmatrix.sync.aligned.m8n8.x4.shared.b16 {%0,%1,%2,%3}, [%4];"
                 : "=r"(r[0]), "=r"(r[1]), "=r"(r[2]), "=r"(r[3]) : "r"(addr));
}

__device__ __forceinline__ void mma8(float* c, const uint32_t* a, const uint32_t* b) {
    asm volatile(
        "mma.sync.aligned.m16n8k8.row.col.f32.tf32.tf32.f32 "
        "{%0,%1,%2,%3}, {%4,%5,%6,%7}, {%8,%9}, {%0,%1,%2,%3};"
        : "+f"(c[0]), "+f"(c[1]), "+f"(c[2]), "+f"(c[3])
        : "r"(a[0]), "r"(a[1]), "r"(a[2]), "r"(a[3]),
          "r"(b[0]), "r"(b[1]));
}

// ---------------- NT GEMM (mma.sync tf32 + ldmatrix + cp.async) -------------
// C[M,N] = f(alpha * A[M,K] * B[N,K]^T) per epilogue mode.
// A, B K-major, tf32-pre-rounded. M%128==0, N%256==0, K%32==0 (K>=96).
// 256 threads, 8 warps (2 m x 4 n), warp tile 64x64, 3-stage cp.async.
__global__ __launch_bounds__(256, 1)
void gemm_nt_mma(const float* __restrict__ A, const float* __restrict__ B,
                 const float* __restrict__ bias, float* __restrict__ C,
                 int N, int K, float alpha, int mode, int rndOut,
                 float* __restrict__ aux,
                 size_t strA, size_t strB, size_t strC)
{
    extern __shared__ char smem[];
    const uint32_t sbase = smem_u32(smem);

    A += (size_t)blockIdx.z * strA;
    B += (size_t)blockIdx.z * strB;
    C += (size_t)blockIdx.z * strC;

    const int tid  = threadIdx.x;
    const int lane = tid & 31;
    const int wid  = tid >> 5;
    const int wm   = wid & 1;          // 2 warps along M (64 rows each)
    const int wn   = wid >> 1;         // 4 warps along N (64 cols each)
    const int m0   = blockIdx.y * BM;
    const int n0   = blockIdx.x * BN;

    float acc[4][8][4];
#pragma unroll
    for (int i = 0; i < 4; i++)
#pragma unroll
        for (int j = 0; j < 8; j++)
#pragma unroll
            for (int r = 0; r < 4; r++) acc[i][j][r] = 0.f;

    // loader lane mapping: 16B chunk lc of row lr (+p*32)
    const int lr = tid >> 3;           // 0..31
    const int lc = tid & 7;            // 0..7

    // ldmatrix lane address bases
    const int arow = (lane & 7) + ((lane >> 3) & 1) * 8;
    const int acol = ((lane >> 4) & 1) * 16;
    const int brow = (lane & 7) + ((lane >> 4) & 1) * 8;
    const int bcol = ((lane >> 3) & 1) * 16;
    const uint32_t xmask = (uint32_t)((lane & 7) << 4);

    uint32_t abase[4], bbase[4];
#pragma unroll
    for (int mi = 0; mi < 4; mi++)
        abase[mi] = (uint32_t)((wm * 64 + mi * 16 + arow) * 128 + acol);
#pragma unroll
    for (int q = 0; q < 4; q++)
        bbase[q] = (uint32_t)((wn * 64 + q * 16 + brow) * 128 + bcol);

    auto loadStage = [&](int i, int s) {
        const uint32_t baseA = sbase + (uint32_t)s * STAGEB;
        const uint32_t baseB = baseA + ASTAGE;
        const float* Ag = A + (size_t)m0 * K + (size_t)i * BK + lc * 4;
        const float* Bg = B + (size_t)n0 * K + (size_t)i * BK + lc * 4;
#pragma unroll
        for (int p = 0; p < 4; p++) {
            const int r = p * 32 + lr;
            CP_ASYNC16(baseA + (uint32_t)(r * 128 + ((lc ^ (r & 7)) * 16)),
                       Ag + (size_t)r * K);
        }
#pragma unroll
        for (int p = 0; p < 8; p++) {
            const int r = p * 32 + lr;
            CP_ASYNC16(baseB + (uint32_t)(r * 128 + ((lc ^ (r & 7)) * 16)),
                       Bg + (size_t)r * K);
        }
    };

    const int nIter = K / BK;
    loadStage(0, 0); CP_COMMIT();
    loadStage(1, 1); CP_COMMIT();

    int s = 0;
    for (int i = 0; i < nIter; i++) {
        CP_WAIT1();
        __syncthreads();

        const uint32_t aS = sbase + (uint32_t)s * STAGEB;
        const uint32_t bS = aS + ASTAGE;
#pragma unroll
        for (int kk = 0; kk < 4; kk++) {
            uint32_t a[4][4];
            uint32_t b[8][2];
#pragma unroll
            for (int mi = 0; mi < 4; mi++)
                ldsm4(a[mi], aS + ((abase[mi] + kk * 32) ^ xmask));
#pragma unroll
            for (int q = 0; q < 4; q++) {
                uint32_t r[4];
                ldsm4(r, bS + ((bbase[q] + kk * 32) ^ xmask));
                b[2 * q][0]     = r[0]; b[2 * q][1]     = r[1];
                b[2 * q + 1][0] = r[2]; b[2 * q + 1][1] = r[3];
            }
#pragma unroll
            for (int mi = 0; mi < 4; mi++)
#pragma unroll
                for (int ni = 0; ni < 8; ni++)
                    mma8(acc[mi][ni], a[mi], b[ni]);
        }

        if (i + 2 < nIter) {
            int s2 = s + 2; if (s2 >= 3) s2 -= 3;
            loadStage(i + 2, s2);
        }
        CP_COMMIT();
        s++; if (s == 3) s = 0;
    }

    // ---- epilogues ----
    const int g  = lane >> 2;
    const int tg = lane & 3;
    // global row base for aux indexing (rows counted across grid y*z)
    const int growBase = blockIdx.z * (gridDim.y * BM) + m0 + wm * 64;

    if (mode == MODE_TRANSV) {
        // stage C^T through smem (stride 129: conflict-free), then coalesced Vt rows.
        // Safe to reuse smem: all non-empty cp.async groups were drained by the
        // final CP_WAIT1 (trailing commits are empty), and __syncthreads orders
        // the last ldmatrix reads before the stores below.
        __syncthreads();
        float* sf = (float*)smem;
#pragma unroll
        for (int mi = 0; mi < 4; mi++) {
            const int mr = wm * 64 + mi * 16 + g;
#pragma unroll
            for (int ni = 0; ni < 8; ni++) {
                const int ncl = wn * 64 + ni * 8 + 2 * tg;
                const int ncg = n0 + ncl;
                float b0 = __ldg(bias + ncg), b1 = __ldg(bias + ncg + 1);
                sf[(ncl)     * 129 + mr]     = tf32r(acc[mi][ni][0] + b0);
                sf[(ncl + 1) * 129 + mr]     = tf32r(acc[mi][ni][1] + b1);
                sf[(ncl)     * 129 + mr + 8] = tf32r(acc[mi][ni][2] + b0);
                sf[(ncl + 1) * 129 + mr + 8] = tf32r(acc[mi][ni][3] + b1);
            }
        }
        __syncthreads();
        const int b  = m0 >> 11;           // batch (SEQ = 2048 rows)
        const int s0 = m0 & 2047;
        float* dst = C + (size_t)b * DIM * SEQ + (size_t)(n0 + tid) * SEQ + s0;
        const float* src = sf + (size_t)tid * 129;
#pragma unroll
        for (int m4 = 0; m4 < 128; m4 += 4) {
            float4 v = make_float4(src[m4], src[m4 + 1], src[m4 + 2], src[m4 + 3]);
            *(float4*)(dst + m4) = v;
        }
        return;
    }

    if (mode == MODE_EXP) {
        float rs[4][2];
#pragma unroll
        for (int mi = 0; mi < 4; mi++) { rs[mi][0] = 0.f; rs[mi][1] = 0.f; }
#pragma unroll
        for (int mi = 0; mi < 4; mi++) {
            const int mrow = m0 + wm * 64 + mi * 16 + g;
#pragma unroll
            for (int ni = 0; ni < 8; ni++) {
                const int nc = n0 + wn * 64 + ni * 8 + 2 * tg;
                float e00 = tf32r(__expf(acc[mi][ni][0] * alpha));
                float e01 = tf32r(__expf(acc[mi][ni][1] * alpha));
                float e10 = tf32r(__expf(acc[mi][ni][2] * alpha));
                float e11 = tf32r(__expf(acc[mi][ni][3] * alpha));
                rs[mi][0] += e00 + e01;
                rs[mi][1] += e10 + e11;
                *(float2*)&C[(size_t)mrow * N + nc]       = make_float2(e00, e01);
                *(float2*)&C[(size_t)(mrow + 8) * N + nc] = make_float2(e10, e11);
            }
        }
        // reduce across tg lanes (same g), then one lane writes per row slice
        const int slot = blockIdx.x * 4 + wn;
#pragma unroll
        for (int mi = 0; mi < 4; mi++) {
#pragma unroll
            for (int h = 0; h < 2; h++) {
                float v = rs[mi][h];
                v += __shfl_xor_sync(0xffffffffu, v, 1);
                v += __shfl_xor_sync(0xffffffffu, v, 2);
                if (tg == 0) {
                    const int grow = growBase + mi * 16 + g + h * 8;
                    aux[(size_t)grow * 32 + slot] = v;
                }
            }
        }
        return;
    }

    // MODE_PLAIN / MODE_NORM
#pragma unroll
    for (int mi = 0; mi < 4; mi++) {
        const int mrow = m0 + wm * 64 + mi * 16 + g;
        float inv0 = 1.f, inv1 = 1.f;
        if (mode == MODE_NORM) {
            const int grow = growBase + mi * 16 + g;
            inv0 = __ldg(aux + grow);
            inv1 = __ldg(aux + grow + 8);
        }
#pragma unroll
        for (int ni = 0; ni < 8; ni++) {
            const int nc = n0 + wn * 64 + ni * 8 + 2 * tg;
            float b0 = 0.f, b1 = 0.f;
            if (bias) { b0 = __ldg(bias + nc); b1 = __ldg(bias + nc + 1); }
            float2 r0, r1;
            if (mode == MODE_NORM) {
                r0 = make_float2(acc[mi][ni][0] * inv0, acc[mi][ni][1] * inv0);
                r1 = make_float2(acc[mi][ni][2] * inv1, acc[mi][ni][3] * inv1);
            } else {
                r0 = make_float2(acc[mi][ni][0] * alpha + b0, acc[mi][ni][1] * alpha + b1);
                r1 = make_float2(acc[mi][ni][2] * alpha + b0, acc[mi][ni][3] * alpha + b1);
            }
            if (rndOut) {
                r0.x = tf32r(r0.x); r0.y = tf32r(r0.y);
                r1.x = tf32r(r1.x); r1.y = tf32r(r1.y);
            }
            *(float2*)&C[(size_t)mrow * N + nc]       = r0;
            *(float2*)&C[(size_t)(mrow + 8) * N + nc] = r1;
        }
    }
}

// ---------------- aux kernels ----------------------------------------------

// tf32-round copy (prepares x for the projection GEMMs)
__global__ __launch_bounds__(256)
void round_copy4(const float4* __restrict__ in, float4* __restrict__ out, int n4)
{
    int i = blockIdx.x * 256 + threadIdx.x;
    if (i < n4) {
        float4 v = in[i];
        v.x = tf32r(v.x); v.y = tf32r(v.y); v.z = tf32r(v.z); v.w = tf32r(v.w);
        out[i] = v;
    }
}

// out[C,R] = in[R,C]^T tf32-rounded; R,C multiples of 32
__global__ __launch_bounds__(256)
void transpose32(const float* __restrict__ in, float* __restrict__ out, int R, int C)
{
    __shared__ float t[32][33];
    const int x  = blockIdx.x * 32 + threadIdx.x;
    const int y0 = blockIdx.y * 32;
#pragma unroll
    for (int j = threadIdx.y; j < 32; j += 8)
        t[j][threadIdx.x] = tf32r(in[(size_t)(y0 + j) * C + x]);
    __syncthreads();
    const int ox  = y0 + threadIdx.x;
    const int oy0 = blockIdx.x * 32;
#pragma unroll
    for (int j = threadIdx.y; j < 32; j += 8)
        out[(size_t)(oy0 + j) * R + ox] = t[threadIdx.x][j];
}

// inv[r] = 1 / sum(partial[r][0..31])
__global__ __launch_bounds__(256)
void rowsum_inv(const float* __restrict__ partial, float* __restrict__ inv, int rows)
{
    int r = blockIdx.x * 256 + threadIdx.x;
    if (r < rows) {
        const float4* p = (const float4*)(partial + (size_t)r * 32);
        float s = 0.f;
#pragma unroll
        for (int i = 0; i < 8; i++) {
            float4 v = p[i];
            s += (v.x + v.y) + (v.z + v.w);
        }
        inv[r] = 1.0f / s;
    }
}

// ---------------- launch ----------------------------------------------------
extern "C" void kernel_launch(void* const* d_in, const int* in_sizes, int n_in,
                              void* d_out, int out_size)
{
    const float* x  = (const float*)d_in[0];
    const float* Wq = (const float*)d_in[1];
    const float* bq = (const float*)d_in[2];
    const float* Wk = (const float*)d_in[3];
    const float* bk = (const float*)d_in[4];
    const float* Wv = (const float*)d_in[5];
    const float* bv = (const float*)d_in[6];
    const float* Wo = (const float*)d_in[7];
    const float* bo = (const float*)d_in[8];
    float* out = (float*)d_out;

    float *X, *Q, *K, *Vt, *P, *C, *Wt, *PS, *INV;
    cudaGetSymbolAddress((void**)&X,   g_X);
    cudaGetSymbolAddress((void**)&Q,   g_Q);
    cudaGetSymbolAddress((void**)&K,   g_K);
    cudaGetSymbolAddress((void**)&Vt,  g_Vt);
    cudaGetSymbolAddress((void**)&P,   g_P);
    cudaGetSymbolAddress((void**)&C,   g_C);
    cudaGetSymbolAddress((void**)&Wt,  g_Wt);
    cudaGetSymbolAddress((void**)&PS,  g_ps);
    cudaGetSymbolAddress((void**)&INV, g_inv);

    cudaFuncSetAttribute(gemm_nt_mma, cudaFuncAttributeMaxDynamicSharedMemorySize, GEMM_SMEM);

    const float scale = 1.0f / 32.0f;   // 1/sqrt(1024)
    dim3 tb(32, 8);
    dim3 gT(DIM / 32, DIM / 32, 1);

    // 1) tf32-round x
    round_copy4<<<(MTOT * DIM / 4 + 255) / 256, 256>>>((const float4*)x, (float4*)X, MTOT * DIM / 4);

    // 2) transpose + round weights: Wt[i] is [N,K] K-major
    transpose32<<<gT, tb>>>(Wq, Wt + 0 * (size_t)DIM * DIM, DIM, DIM);
    transpose32<<<gT, tb>>>(Wk, Wt + 1 * (size_t)DIM * DIM, DIM, DIM);
    transpose32<<<gT, tb>>>(Wv, Wt + 2 * (size_t)DIM * DIM, DIM, DIM);
    transpose32<<<gT, tb>>>(Wo, Wt + 3 * (size_t)DIM * DIM, DIM, DIM);

    dim3 g_proj(DIM / BN, MTOT / BM, 1);     // 4 x 64
    dim3 g_sc(SEQ / BN, SEQ / BM, NB);       // 8 x 16 x 4
    dim3 g_ctx(DIM / BN, SEQ / BM, NB);      // 4 x 16 x 4

    // 3) Q/K projections (tf32-rounded); V projection writes Vt transposed
    gemm_nt_mma<<<g_proj, 256, GEMM_SMEM>>>(X, Wt + 0 * (size_t)DIM * DIM, bq, Q,
                                            DIM, DIM, 1.f, MODE_PLAIN, 1, nullptr, 0, 0, 0);
    gemm_nt_mma<<<g_proj, 256, GEMM_SMEM>>>(X, Wt + 1 * (size_t)DIM * DIM, bk, K,
                                            DIM, DIM, 1.f, MODE_PLAIN, 1, nullptr, 0, 0, 0);
    gemm_nt_mma<<<g_proj, 256, GEMM_SMEM>>>(X, Wt + 2 * (size_t)DIM * DIM, bv, Vt,
                                            DIM, DIM, 1.f, MODE_TRANSV, 1, nullptr, 0, 0, 0);

    // 4) expP = exp(scale * Q K^T), partial row sums (no separate softmax pass)
    gemm_nt_mma<<<g_sc, 256, GEMM_SMEM>>>(Q, K, nullptr, P, SEQ, DIM, scale,
                                          MODE_EXP, 1, PS,
                                          (size_t)SEQ * DIM, (size_t)SEQ * DIM, (size_t)SEQ * SEQ);

    // 5) inv row sums
    rowsum_inv<<<MTOT / 256, 256>>>(PS, INV, MTOT);

    // 6) ctx = (expP * V) * inv   (A=P [S,S], B=Vt [D,S])
    gemm_nt_mma<<<g_ctx, 256, GEMM_SMEM>>>(P, Vt, nullptr, C, DIM, SEQ, 1.f,
                                           MODE_NORM, 1, INV,
                                           (size_t)SEQ * SEQ, (size_t)SEQ * DIM, (size_t)SEQ * DIM);

    // 7) out = ctx * Wo + bo (final fp32, no rounding)
    gemm_nt_mma<<<g_proj, 256, GEMM_SMEM>>>(C, Wt + 3 * (size_t)DIM * DIM, bo, out,
                                            DIM, DIM, 1.f, MODE_PLAIN, 0, nullptr, 0, 0, 0);
}

// round 9
// speedup vs baseline: 2.1670x; 1.5615x over previous
#include <cuda_runtime.h>
#include <cuda_fp16.h>
#include <cstdint>

// Problem constants
#define NB   4
#define SEQ  2048
#define DIM  1024
#define MTOT (NB * SEQ)   // 8192

// GEMM tiling (fp16 operands)
#define BM 128
#define BN 256
#define BK 64                            // 64 halves = 128 B per row slab
#define ASTAGE (BM * BK * 2)             // 16384 B
#define BSTAGE (BN * BK * 2)             // 32768 B
#define STAGEB (ASTAGE + BSTAGE)         // 49152 B
#define GEMM_SMEM (3 * STAGEB)           // 147456 B (3 stages; covers 256*129*4 staging)

// Epilogue modes
#define MODE_PLAIN 0   // C = alpha*acc + bias            (outHalf ? half : float)
#define MODE_EXP   1   // C = h(exp(alpha*acc)); aux = partial row sums [rows][32]
#define MODE_NORM  2   // C = h(acc * aux[row])           (aux = inv row sums)
#define MODE_TRANSV 3  // C^T write (Vt half): bias, per-batch [DIM][SEQ]

// ---------------- scratch (__device__ globals; no allocation allowed) ------
__device__ __half g_X [(size_t)MTOT * DIM];
__device__ __half g_Q [(size_t)MTOT * DIM];
__device__ __half g_K [(size_t)MTOT * DIM];
__device__ __half g_Vt[(size_t)MTOT * DIM];
__device__ __half g_P [(size_t)NB * SEQ * SEQ];
__device__ __half g_C [(size_t)MTOT * DIM];
__device__ __half g_Wt[(size_t)4 * DIM * DIM];
__device__ float  g_ps[(size_t)MTOT * 32];
__device__ float  g_inv[(size_t)MTOT];

// ---------------- helpers ---------------------------------------------------
__device__ __forceinline__ uint32_t smem_u32(const void* p) {
    uint32_t a;
    asm("{ .reg .u64 t; cvta.to.shared.u64 t, %1; cvt.u32.u64 %0, t; }" : "=r"(a) : "l"(p));
    return a;
}

__device__ __forceinline__ uint32_t h2pack(float a, float b) {
    __half2 h = __floats2half2_rn(a, b);
    return *(uint32_t*)&h;
}

#define CP_ASYNC16(dst, src) \
    asm volatile("cp.async.cg.shared.global [%0], [%1], 16;" :: "r"(dst), "l"(src) : "memory")
#define CP_COMMIT() asm volatile("cp.async.commit_group;" ::: "memory")
#define CP_WAIT1()  asm volatile("cp.async.wait_group 1;" ::: "memory")

__device__ __forceinline__ void ldsm4(uint32_t* r, uint32_t addr) {
    asm volatile("ldmatrix.sync.aligned.m8n8.x4.shared.b16 {%0,%1,%2,%3}, [%4];"
                 : "=r"(r[0]), "=r"(r[1]), "=r"(r[2]), "=r"(r[3]) : "r"(addr));
}

// m16n8k16 fp16, fp32 accumulate
__device__ __forceinline__ void mma16(float* c, const uint32_t* a, const uint32_t* b) {
    asm volatile(
        "mma.sync.aligned.m16n8k16.row.col.f32.f16.f16.f32 "
        "{%0,%1,%2,%3}, {%4,%5,%6,%7}, {%8,%9}, {%0,%1,%2,%3};"
        : "+f"(c[0]), "+f"(c[1]), "+f"(c[2]), "+f"(c[3])
        : "r"(a[0]), "r"(a[1]), "r"(a[2]), "r"(a[3]),
          "r"(b[0]), "r"(b[1]));
}

// ---------------- NT GEMM (mma.sync fp16 + ldmatrix + cp.async) -------------
// acc[M,N] = A[M,K] * B[N,K]^T ; epilogue per mode.
// A, B K-major fp16. M%128==0, N%256==0, K%64==0 (K>=192).
// 256 threads, 8 warps (2 m x 4 n), warp tile 64x64, 3-stage cp.async.
__global__ __launch_bounds__(256, 1)
void gemm_nt_mma(const __half* __restrict__ A, const __half* __restrict__ B,
                 const float* __restrict__ bias, void* __restrict__ Cv,
                 int N, int K, float alpha, int mode, int outHalf,
                 float* __restrict__ aux,
                 size_t strA, size_t strB, size_t strC)
{
    extern __shared__ char smem[];
    const uint32_t sbase = smem_u32(smem);

    A += (size_t)blockIdx.z * strA;
    B += (size_t)blockIdx.z * strB;
    __half* Ch = (__half*)Cv + (size_t)blockIdx.z * strC;
    float*  Cf = (float*)Cv  + (size_t)blockIdx.z * strC;

    const int tid  = threadIdx.x;
    const int lane = tid & 31;
    const int wid  = tid >> 5;
    const int wm   = wid & 1;          // 2 warps along M (64 rows each)
    const int wn   = wid >> 1;         // 4 warps along N (64 cols each)
    const int m0   = blockIdx.y * BM;
    const int n0   = blockIdx.x * BN;

    float acc[4][8][4];
#pragma unroll
    for (int i = 0; i < 4; i++)
#pragma unroll
        for (int j = 0; j < 8; j++)
#pragma unroll
            for (int r = 0; r < 4; r++) acc[i][j][r] = 0.f;

    // loader lane mapping: 16B chunk lc (8 halves) of row lr (+p*32)
    const int lr = tid >> 3;           // 0..31
    const int lc = tid & 7;            // 0..7

    // ldmatrix octet mapping (same for A and B):
    // tile0: rows +0, col +0B | tile1: rows +8, col +0B
    // tile2: rows +0, col +16B| tile3: rows +8, col +16B
    const int lrow = (lane & 7) + ((lane >> 3) & 1) * 8;
    const int lcol = ((lane >> 4) & 1) * 16;
    const uint32_t xmask = (uint32_t)((lane & 7) << 4);   // swizzle XOR (row&7)

    uint32_t abase[4], bbase[4];
#pragma unroll
    for (int mi = 0; mi < 4; mi++)
        abase[mi] = (uint32_t)((wm * 64 + mi * 16 + lrow) * 128 + lcol);
#pragma unroll
    for (int q = 0; q < 4; q++)
        bbase[q] = (uint32_t)((wn * 64 + q * 16 + lrow) * 128 + lcol);

    auto loadStage = [&](int i, int s) {
        const uint32_t baseA = sbase + (uint32_t)s * STAGEB;
        const uint32_t baseB = baseA + ASTAGE;
        const __half* Ag = A + (size_t)m0 * K + (size_t)i * BK + lc * 8;
        const __half* Bg = B + (size_t)n0 * K + (size_t)i * BK + lc * 8;
#pragma unroll
        for (int p = 0; p < 4; p++) {
            const int r = p * 32 + lr;
            CP_ASYNC16(baseA + (uint32_t)(r * 128 + ((lc ^ (r & 7)) * 16)),
                       (const void*)(Ag + (size_t)r * K));
        }
#pragma unroll
        for (int p = 0; p < 8; p++) {
            const int r = p * 32 + lr;
            CP_ASYNC16(baseB + (uint32_t)(r * 128 + ((lc ^ (r & 7)) * 16)),
                       (const void*)(Bg + (size_t)r * K));
        }
    };

    const int nIter = K / BK;
    loadStage(0, 0); CP_COMMIT();
    loadStage(1, 1); CP_COMMIT();

    int s = 0;
    for (int i = 0; i < nIter; i++) {
        CP_WAIT1();
        __syncthreads();

        const uint32_t aS = sbase + (uint32_t)s * STAGEB;
        const uint32_t bS = aS + ASTAGE;
#pragma unroll
        for (int kk = 0; kk < 4; kk++) {        // kk covers 16 halves = 32 B
            uint32_t a[4][4];
            uint32_t b[8][2];
#pragma unroll
            for (int mi = 0; mi < 4; mi++)
                ldsm4(a[mi], aS + ((abase[mi] + kk * 32) ^ xmask));
#pragma unroll
            for (int q = 0; q < 4; q++) {
                uint32_t r[4];
                ldsm4(r, bS + ((bbase[q] + kk * 32) ^ xmask));
                // r0=(n0-7,k0-7) r1=(n8-15,k0-7) r2=(n0-7,k8-15) r3=(n8-15,k8-15)
                b[2 * q][0]     = r[0]; b[2 * q][1]     = r[2];
                b[2 * q + 1][0] = r[1]; b[2 * q + 1][1] = r[3];
            }
#pragma unroll
            for (int mi = 0; mi < 4; mi++)
#pragma unroll
                for (int ni = 0; ni < 8; ni++)
                    mma16(acc[mi][ni], a[mi], b[ni]);
        }

        if (i + 2 < nIter) {
            int s2 = s + 2; if (s2 >= 3) s2 -= 3;
            loadStage(i + 2, s2);
        }
        CP_COMMIT();
        s++; if (s == 3) s = 0;
    }

    // ---- epilogues ----
    const int g  = lane >> 2;
    const int tg = lane & 3;
    const int growBase = blockIdx.z * (gridDim.y * BM) + m0 + wm * 64;

    if (mode == MODE_TRANSV) {
        // stage C^T through smem (float, stride 129), then coalesced half Vt rows
        __syncthreads();
        float* sf = (float*)smem;
#pragma unroll
        for (int mi = 0; mi < 4; mi++) {
            const int mr = wm * 64 + mi * 16 + g;
#pragma unroll
            for (int ni = 0; ni < 8; ni++) {
                const int ncl = wn * 64 + ni * 8 + 2 * tg;
                const int ncg = n0 + ncl;
                float b0 = __ldg(bias + ncg), b1 = __ldg(bias + ncg + 1);
                sf[(ncl)     * 129 + mr]     = acc[mi][ni][0] + b0;
                sf[(ncl + 1) * 129 + mr]     = acc[mi][ni][1] + b1;
                sf[(ncl)     * 129 + mr + 8] = acc[mi][ni][2] + b0;
                sf[(ncl + 1) * 129 + mr + 8] = acc[mi][ni][3] + b1;
            }
        }
        __syncthreads();
        const int b  = m0 >> 11;           // batch (SEQ = 2048 rows)
        const int s0 = m0 & 2047;
        __half* dst = Ch + (size_t)b * DIM * SEQ + (size_t)(n0 + tid) * SEQ + s0;
        const float* src = sf + (size_t)tid * 129;
#pragma unroll
        for (int m4 = 0; m4 < 128; m4 += 4) {
            uint2 v;
            v.x = h2pack(src[m4],     src[m4 + 1]);
            v.y = h2pack(src[m4 + 2], src[m4 + 3]);
            *(uint2*)(dst + m4) = v;
        }
        return;
    }

    if (mode == MODE_EXP) {
        float rs[4][2];
#pragma unroll
        for (int mi = 0; mi < 4; mi++) { rs[mi][0] = 0.f; rs[mi][1] = 0.f; }
#pragma unroll
        for (int mi = 0; mi < 4; mi++) {
            const int mrow = m0 + wm * 64 + mi * 16 + g;
#pragma unroll
            for (int ni = 0; ni < 8; ni++) {
                const int nc = n0 + wn * 64 + ni * 8 + 2 * tg;
                __half2 h0 = __floats2half2_rn(__expf(acc[mi][ni][0] * alpha),
                                               __expf(acc[mi][ni][1] * alpha));
                __half2 h1 = __floats2half2_rn(__expf(acc[mi][ni][2] * alpha),
                                               __expf(acc[mi][ni][3] * alpha));
                float2 f0 = __half22float2(h0);
                float2 f1 = __half22float2(h1);
                rs[mi][0] += f0.x + f0.y;
                rs[mi][1] += f1.x + f1.y;
                *(__half2*)&Ch[(size_t)mrow * N + nc]       = h0;
                *(__half2*)&Ch[(size_t)(mrow + 8) * N + nc] = h1;
            }
        }
        const int slot = blockIdx.x * 4 + wn;
#pragma unroll
        for (int mi = 0; mi < 4; mi++) {
#pragma unroll
            for (int h = 0; h < 2; h++) {
                float v = rs[mi][h];
                v += __shfl_xor_sync(0xffffffffu, v, 1);
                v += __shfl_xor_sync(0xffffffffu, v, 2);
                if (tg == 0) {
                    const int grow = growBase + mi * 16 + g + h * 8;
                    aux[(size_t)grow * 32 + slot] = v;
                }
            }
        }
        return;
    }

    // MODE_PLAIN / MODE_NORM
#pragma unroll
    for (int mi = 0; mi < 4; mi++) {
        const int mrow = m0 + wm * 64 + mi * 16 + g;
        float inv0 = 1.f, inv1 = 1.f;
        if (mode == MODE_NORM) {
            const int grow = growBase + mi * 16 + g;
            inv0 = __ldg(aux + grow);
            inv1 = __ldg(aux + grow + 8);
        }
#pragma unroll
        for (int ni = 0; ni < 8; ni++) {
            const int nc = n0 + wn * 64 + ni * 8 + 2 * tg;
            float b0 = 0.f, b1 = 0.f;
            if (bias) { b0 = __ldg(bias + nc); b1 = __ldg(bias + nc + 1); }
            float2 r0, r1;
            if (mode == MODE_NORM) {
                r0 = make_float2(acc[mi][ni][0] * inv0, acc[mi][ni][1] * inv0);
                r1 = make_float2(acc[mi][ni][2] * inv1, acc[mi][ni][3] * inv1);
            } else {
                r0 = make_float2(acc[mi][ni][0] * alpha + b0, acc[mi][ni][1] * alpha + b1);
                r1 = make_float2(acc[mi][ni][2] * alpha + b0, acc[mi][ni][3] * alpha + b1);
            }
            if (outHalf) {
                *(uint32_t*)&Ch[(size_t)mrow * N + nc]       = h2pack(r0.x, r0.y);
                *(uint32_t*)&Ch[(size_t)(mrow + 8) * N + nc] = h2pack(r1.x, r1.y);
            } else {
                *(float2*)&Cf[(size_t)mrow * N + nc]       = r0;
                *(float2*)&Cf[(size_t)(mrow + 8) * N + nc] = r1;
            }
        }
    }
}

// ---------------- aux kernels ----------------------------------------------

// fp32 -> fp16 copy (prepares x for the projection GEMMs)
__global__ __launch_bounds__(256)
void half_copy4(const float4* __restrict__ in, uint2* __restrict__ out, int n4)
{
    int i = blockIdx.x * 256 + threadIdx.x;
    if (i < n4) {
        float4 v = in[i];
        uint2 o;
        o.x = h2pack(v.x, v.y);
        o.y = h2pack(v.z, v.w);
        out[i] = o;
    }
}

// out[C,R] = half(in[R,C]^T); R,C multiples of 32
__global__ __launch_bounds__(256)
void transpose32h(const float* __restrict__ in, __half* __restrict__ out, int R, int C)
{
    __shared__ float t[32][33];
    const int x  = blockIdx.x * 32 + threadIdx.x;
    const int y0 = blockIdx.y * 32;
#pragma unroll
    for (int j = threadIdx.y; j < 32; j += 8)
        t[j][threadIdx.x] = in[(size_t)(y0 + j) * C + x];
    __syncthreads();
    const int ox  = y0 + threadIdx.x;
    const int oy0 = blockIdx.x * 32;
#pragma unroll
    for (int j = threadIdx.y; j < 32; j += 8)
        out[(size_t)(oy0 + j) * R + ox] = __float2half_rn(t[threadIdx.x][j]);
}

// inv[r] = 1 / sum(partial[r][0..31])
__global__ __launch_bounds__(256)
void rowsum_inv(const float* __restrict__ partial, float* __restrict__ inv, int rows)
{
    int r = blockIdx.x * 256 + threadIdx.x;
    if (r < rows) {
        const float4* p = (const float4*)(partial + (size_t)r * 32);
        float s = 0.f;
#pragma unroll
        for (int i = 0; i < 8; i++) {
            float4 v = p[i];
            s += (v.x + v.y) + (v.z + v.w);
        }
        inv[r] = 1.0f / s;
    }
}

// ---------------- launch ----------------------------------------------------
extern "C" void kernel_launch(void* const* d_in, const int* in_sizes, int n_in,
                              void* d_out, int out_size)
{
    const float* x  = (const float*)d_in[0];
    const float* Wq = (const float*)d_in[1];
    const float* bq = (const float*)d_in[2];
    const float* Wk = (const float*)d_in[3];
    const float* bk = (const float*)d_in[4];
    const float* Wv = (const float*)d_in[5];
    const float* bv = (const float*)d_in[6];
    const float* Wo = (const float*)d_in[7];
    const float* bo = (const float*)d_in[8];
    float* out = (float*)d_out;

    __half *X, *Q, *K, *Vt, *P, *C, *Wt;
    float *PS, *INV;
    cudaGetSymbolAddress((void**)&X,   g_X);
    cudaGetSymbolAddress((void**)&Q,   g_Q);
    cudaGetSymbolAddress((void**)&K,   g_K);
    cudaGetSymbolAddress((void**)&Vt,  g_Vt);
    cudaGetSymbolAddress((void**)&P,   g_P);
    cudaGetSymbolAddress((void**)&C,   g_C);
    cudaGetSymbolAddress((void**)&Wt,  g_Wt);
    cudaGetSymbolAddress((void**)&PS,  g_ps);
    cudaGetSymbolAddress((void**)&INV, g_inv);

    cudaFuncSetAttribute(gemm_nt_mma, cudaFuncAttributeMaxDynamicSharedMemorySize, GEMM_SMEM);

    const float scale = 1.0f / 32.0f;   // 1/sqrt(1024)
    dim3 tb(32, 8);
    dim3 gT(DIM / 32, DIM / 32, 1);

    // 1) fp16 x
    half_copy4<<<(MTOT * DIM / 4 + 255) / 256, 256>>>((const float4*)x, (uint2*)X, MTOT * DIM / 4);

    // 2) transpose weights to [N,K] K-major fp16
    transpose32h<<<gT, tb>>>(Wq, Wt + 0 * (size_t)DIM * DIM, DIM, DIM);
    transpose32h<<<gT, tb>>>(Wk, Wt + 1 * (size_t)DIM * DIM, DIM, DIM);
    transpose32h<<<gT, tb>>>(Wv, Wt + 2 * (size_t)DIM * DIM, DIM, DIM);
    transpose32h<<<gT, tb>>>(Wo, Wt + 3 * (size_t)DIM * DIM, DIM, DIM);

    dim3 g_proj(DIM / BN, MTOT / BM, 1);     // 4 x 64
    dim3 g_sc(SEQ / BN, SEQ / BM, NB);       // 8 x 16 x 4
    dim3 g_ctx(DIM / BN, SEQ / BM, NB);      // 4 x 16 x 4

    // 3) Q/K projections (half out); V projection writes Vt transposed (half)
    gemm_nt_mma<<<g_proj, 256, GEMM_SMEM>>>(X, Wt + 0 * (size_t)DIM * DIM, bq, Q,
                                            DIM, DIM, 1.f, MODE_PLAIN, 1, nullptr, 0, 0, 0);
    gemm_nt_mma<<<g_proj, 256, GEMM_SMEM>>>(X, Wt + 1 * (size_t)DIM * DIM, bk, K,
                                            DIM, DIM, 1.f, MODE_PLAIN, 1, nullptr, 0, 0, 0);
    gemm_nt_mma<<<g_proj, 256, GEMM_SMEM>>>(X, Wt + 2 * (size_t)DIM * DIM, bv, Vt,
                                            DIM, DIM, 1.f, MODE_TRANSV, 1, nullptr, 0, 0, 0);

    // 4) expP = exp(scale * Q K^T) (half), partial row sums
    gemm_nt_mma<<<g_sc, 256, GEMM_SMEM>>>(Q, K, nullptr, P, SEQ, DIM, scale,
                                          MODE_EXP, 1, PS,
                                          (size_t)SEQ * DIM, (size_t)SEQ * DIM, (size_t)SEQ * SEQ);

    // 5) inv row sums
    rowsum_inv<<<MTOT / 256, 256>>>(PS, INV, MTOT);

    // 6) ctx = (expP * V) * inv   (A=P [S,S], B=Vt [D,S]) -> half
    gemm_nt_mma<<<g_ctx, 256, GEMM_SMEM>>>(P, Vt, nullptr, C, DIM, SEQ, 1.f,
                                           MODE_NORM, 1, INV,
                                           (size_t)SEQ * SEQ, (size_t)SEQ * DIM, (size_t)SEQ * DIM);

    // 7) out = ctx * Wo + bo (fp32 out)
    gemm_nt_mma<<<g_proj, 256, GEMM_SMEM>>>(C, Wt + 3 * (size_t)DIM * DIM, bo, out,
                                            DIM, DIM, 1.f, MODE_PLAIN, 0, nullptr, 0, 0, 0);
}

// round 10
// speedup vs baseline: 2.2060x; 1.0180x over previous
#include <cuda_runtime.h>
#include <cuda_fp16.h>
#include <cstdint>

// Problem constants
#define NB   4
#define SEQ  2048
#define DIM  1024
#define MTOT (NB * SEQ)   // 8192

// GEMM tiling (fp16 operands), 2 CTAs/SM
#define BM 128
#define BN 128
#define BK 64                            // 64 halves = 128 B per row slab
#define ASTAGE (BM * BK * 2)             // 16384 B
#define BSTAGE (BN * BK * 2)             // 16384 B
#define STAGEB (ASTAGE + BSTAGE)         // 32768 B
#define GEMM_SMEM (3 * STAGEB)           // 98304 B (3 stages; covers 128*129*4 staging)

// Epilogue modes
#define MODE_PLAIN 0   // C = alpha*acc + bias            (outHalf ? half : float)
#define MODE_EXP   1   // C = h(exp(alpha*acc)); aux = partial row sums [rows][64]
#define MODE_NORM  2   // C = h(acc * aux[row])           (aux = inv row sums)
#define MODE_TRANSV 3  // C^T write (Vt half): bias, per-batch [DIM][SEQ]

// ---------------- scratch (__device__ globals; no allocation allowed) ------
__device__ __half g_X [(size_t)MTOT * DIM];
__device__ __half g_Q [(size_t)MTOT * DIM];
__device__ __half g_K [(size_t)MTOT * DIM];
__device__ __half g_Vt[(size_t)MTOT * DIM];
__device__ __half g_P [(size_t)NB * SEQ * SEQ];
__device__ __half g_C [(size_t)MTOT * DIM];
__device__ __half g_Wt[(size_t)4 * DIM * DIM];
__device__ float  g_ps[(size_t)MTOT * 64];
__device__ float  g_inv[(size_t)MTOT];

// ---------------- helpers ---------------------------------------------------
__device__ __forceinline__ uint32_t smem_u32(const void* p) {
    uint32_t a;
    asm("{ .reg .u64 t; cvta.to.shared.u64 t, %1; cvt.u32.u64 %0, t; }" : "=r"(a) : "l"(p));
    return a;
}

__device__ __forceinline__ uint32_t h2pack(float a, float b) {
    __half2 h = __floats2half2_rn(a, b);
    return *(uint32_t*)&h;
}

#define CP_ASYNC16(dst, src) \
    asm volatile("cp.async.cg.shared.global [%0], [%1], 16;" :: "r"(dst), "l"(src) : "memory")
#define CP_COMMIT() asm volatile("cp.async.commit_group;" ::: "memory")
#define CP_WAIT1()  asm volatile("cp.async.wait_group 1;" ::: "memory")

__device__ __forceinline__ void ldsm4(uint32_t* r, uint32_t addr) {
    asm volatile("ldmatrix.sync.aligned.m8n8.x4.shared.b16 {%0,%1,%2,%3}, [%4];"
                 : "=r"(r[0]), "=r"(r[1]), "=r"(r[2]), "=r"(r[3]) : "r"(addr));
}

// m16n8k16 fp16, fp32 accumulate
__device__ __forceinline__ void mma16(float* c, const uint32_t* a, const uint32_t* b) {
    asm volatile(
        "mma.sync.aligned.m16n8k16.row.col.f32.f16.f16.f32 "
        "{%0,%1,%2,%3}, {%4,%5,%6,%7}, {%8,%9}, {%0,%1,%2,%3};"
        : "+f"(c[0]), "+f"(c[1]), "+f"(c[2]), "+f"(c[3])
        : "r"(a[0]), "r"(a[1]), "r"(a[2]), "r"(a[3]),
          "r"(b[0]), "r"(b[1]));
}

// ---------------- NT GEMM (mma.sync fp16 + ldmatrix + cp.async) -------------
// acc[M,N] = A[M,K] * B[N,K]^T ; epilogue per mode.
// A, B K-major fp16. M%128==0, N%128==0, K%64==0 (K>=192).
// 256 threads, 8 warps (2 m x 4 n), warp tile 64x32, 3-stage cp.async,
// 2 CTAs resident per SM.
__global__ __launch_bounds__(256, 2)
void gemm_nt_mma(const __half* __restrict__ A, const __half* __restrict__ B,
                 const float* __restrict__ bias, void* __restrict__ Cv,
                 int N, int K, float alpha, int mode, int outHalf,
                 float* __restrict__ aux,
                 size_t strA, size_t strB, size_t strC)
{
    extern __shared__ char smem[];
    const uint32_t sbase = smem_u32(smem);

    A += (size_t)blockIdx.z * strA;
    B += (size_t)blockIdx.z * strB;
    __half* Ch = (__half*)Cv + (size_t)blockIdx.z * strC;
    float*  Cf = (float*)Cv  + (size_t)blockIdx.z * strC;

    const int tid  = threadIdx.x;
    const int lane = tid & 31;
    const int wid  = tid >> 5;
    const int wm   = wid & 1;          // 2 warps along M (64 rows each)
    const int wn   = wid >> 1;         // 4 warps along N (32 cols each)
    const int m0   = blockIdx.y * BM;
    const int n0   = blockIdx.x * BN;

    float acc[4][4][4];
#pragma unroll
    for (int i = 0; i < 4; i++)
#pragma unroll
        for (int j = 0; j < 4; j++)
#pragma unroll
            for (int r = 0; r < 4; r++) acc[i][j][r] = 0.f;

    // loader lane mapping: 16B chunk lc (8 halves) of row lr (+p*32)
    const int lr = tid >> 3;           // 0..31
    const int lc = tid & 7;            // 0..7

    // ldmatrix octet mapping (same for A and B):
    // tile0: rows +0, col +0B | tile1: rows +8, col +0B
    // tile2: rows +0, col +16B| tile3: rows +8, col +16B
    const int lrow = (lane & 7) + ((lane >> 3) & 1) * 8;
    const int lcol = ((lane >> 4) & 1) * 16;
    const uint32_t xmask = (uint32_t)((lane & 7) << 4);   // swizzle XOR (row&7)

    uint32_t abase[4], bbase[2];
#pragma unroll
    for (int mi = 0; mi < 4; mi++)
        abase[mi] = (uint32_t)((wm * 64 + mi * 16 + lrow) * 128 + lcol);
#pragma unroll
    for (int q = 0; q < 2; q++)
        bbase[q] = (uint32_t)((wn * 32 + q * 16 + lrow) * 128 + lcol);

    auto loadStage = [&](int i, int s) {
        const uint32_t baseA = sbase + (uint32_t)s * STAGEB;
        const uint32_t baseB = baseA + ASTAGE;
        const __half* Ag = A + (size_t)m0 * K + (size_t)i * BK + lc * 8;
        const __half* Bg = B + (size_t)n0 * K + (size_t)i * BK + lc * 8;
#pragma unroll
        for (int p = 0; p < 4; p++) {
            const int r = p * 32 + lr;
            CP_ASYNC16(baseA + (uint32_t)(r * 128 + ((lc ^ (r & 7)) * 16)),
                       (const void*)(Ag + (size_t)r * K));
        }
#pragma unroll
        for (int p = 0; p < 4; p++) {
            const int r = p * 32 + lr;
            CP_ASYNC16(baseB + (uint32_t)(r * 128 + ((lc ^ (r & 7)) * 16)),
                       (const void*)(Bg + (size_t)r * K));
        }
    };

    const int nIter = K / BK;
    loadStage(0, 0); CP_COMMIT();
    loadStage(1, 1); CP_COMMIT();

    int s = 0;
    for (int i = 0; i < nIter; i++) {
        CP_WAIT1();
        __syncthreads();

        const uint32_t aS = sbase + (uint32_t)s * STAGEB;
        const uint32_t bS = aS + ASTAGE;
#pragma unroll
        for (int kk = 0; kk < 4; kk++) {        // kk covers 16 halves = 32 B
            uint32_t a[4][4];
            uint32_t b[4][2];
#pragma unroll
            for (int mi = 0; mi < 4; mi++)
                ldsm4(a[mi], aS + ((abase[mi] + kk * 32) ^ xmask));
#pragma unroll
            for (int q = 0; q < 2; q++) {
                uint32_t r[4];
                ldsm4(r, bS + ((bbase[q] + kk * 32) ^ xmask));
                // r0=(n0-7,k0-7) r1=(n8-15,k0-7) r2=(n0-7,k8-15) r3=(n8-15,k8-15)
                b[2 * q][0]     = r[0]; b[2 * q][1]     = r[2];
                b[2 * q + 1][0] = r[1]; b[2 * q + 1][1] = r[3];
            }
#pragma unroll
            for (int mi = 0; mi < 4; mi++)
#pragma unroll
                for (int ni = 0; ni < 4; ni++)
                    mma16(acc[mi][ni], a[mi], b[ni]);
        }

        if (i + 2 < nIter) {
            int s2 = s + 2; if (s2 >= 3) s2 -= 3;
            loadStage(i + 2, s2);
        }
        CP_COMMIT();
        s++; if (s == 3) s = 0;
    }

    // ---- epilogues ----
    const int g  = lane >> 2;
    const int tg = lane & 3;
    const int growBase = blockIdx.z * (gridDim.y * BM) + m0 + wm * 64;

    if (mode == MODE_TRANSV) {
        // stage C^T through smem (float, stride 129 = conflict-free), then
        // coalesced half Vt rows. Safe: cp.async groups drained, sync below.
        __syncthreads();
        float* sf = (float*)smem;
#pragma unroll
        for (int mi = 0; mi < 4; mi++) {
            const int mr = wm * 64 + mi * 16 + g;
#pragma unroll
            for (int ni = 0; ni < 4; ni++) {
                const int ncl = wn * 32 + ni * 8 + 2 * tg;
                const int ncg = n0 + ncl;
                float b0 = __ldg(bias + ncg), b1 = __ldg(bias + ncg + 1);
                sf[(ncl)     * 129 + mr]     = acc[mi][ni][0] + b0;
                sf[(ncl + 1) * 129 + mr]     = acc[mi][ni][1] + b1;
                sf[(ncl)     * 129 + mr + 8] = acc[mi][ni][2] + b0;
                sf[(ncl + 1) * 129 + mr + 8] = acc[mi][ni][3] + b1;
            }
        }
        __syncthreads();
        // 128 cols x 128 rows; thread tid: col = tid&127, row-half = tid>>7
        const int b  = m0 >> 11;           // batch (SEQ = 2048 rows)
        const int s0 = m0 & 2047;
        const int col  = tid & 127;
        const int rh   = (tid >> 7) * 64;
        __half* dst = Ch + (size_t)b * DIM * SEQ + (size_t)(n0 + col) * SEQ + s0 + rh;
        const float* src = sf + (size_t)col * 129 + rh;
#pragma unroll
        for (int m4 = 0; m4 < 64; m4 += 4) {
            uint2 v;
            v.x = h2pack(src[m4],     src[m4 + 1]);
            v.y = h2pack(src[m4 + 2], src[m4 + 3]);
            *(uint2*)(dst + m4) = v;
        }
        return;
    }

    if (mode == MODE_EXP) {
        float rs[4][2];
#pragma unroll
        for (int mi = 0; mi < 4; mi++) { rs[mi][0] = 0.f; rs[mi][1] = 0.f; }
#pragma unroll
        for (int mi = 0; mi < 4; mi++) {
            const int mrow = m0 + wm * 64 + mi * 16 + g;
#pragma unroll
            for (int ni = 0; ni < 4; ni++) {
                const int nc = n0 + wn * 32 + ni * 8 + 2 * tg;
                __half2 h0 = __floats2half2_rn(__expf(acc[mi][ni][0] * alpha),
                                               __expf(acc[mi][ni][1] * alpha));
                __half2 h1 = __floats2half2_rn(__expf(acc[mi][ni][2] * alpha),
                                               __expf(acc[mi][ni][3] * alpha));
                float2 f0 = __half22float2(h0);
                float2 f1 = __half22float2(h1);
                rs[mi][0] += f0.x + f0.y;
                rs[mi][1] += f1.x + f1.y;
                *(__half2*)&Ch[(size_t)mrow * N + nc]       = h0;
                *(__half2*)&Ch[(size_t)(mrow + 8) * N + nc] = h1;
            }
        }
        const int slot = blockIdx.x * 4 + wn;    // gridDim.x = 16 -> slots 0..63
#pragma unroll
        for (int mi = 0; mi < 4; mi++) {
#pragma unroll
            for (int h = 0; h < 2; h++) {
                float v = rs[mi][h];
                v += __shfl_xor_sync(0xffffffffu, v, 1);
                v += __shfl_xor_sync(0xffffffffu, v, 2);
                if (tg == 0) {
                    const int grow = growBase + mi * 16 + g + h * 8;
                    aux[(size_t)grow * 64 + slot] = v;
                }
            }
        }
        return;
    }

    // MODE_PLAIN / MODE_NORM
#pragma unroll
    for (int mi = 0; mi < 4; mi++) {
        const int mrow = m0 + wm * 64 + mi * 16 + g;
        float inv0 = 1.f, inv1 = 1.f;
        if (mode == MODE_NORM) {
            const int grow = growBase + mi * 16 + g;
            inv0 = __ldg(aux + grow);
            inv1 = __ldg(aux + grow + 8);
        }
#pragma unroll
        for (int ni = 0; ni < 4; ni++) {
            const int nc = n0 + wn * 32 + ni * 8 + 2 * tg;
            float b0 = 0.f, b1 = 0.f;
            if (bias) { b0 = __ldg(bias + nc); b1 = __ldg(bias + nc + 1); }
            float2 r0, r1;
            if (mode == MODE_NORM) {
                r0 = make_float2(acc[mi][ni][0] * inv0, acc[mi][ni][1] * inv0);
                r1 = make_float2(acc[mi][ni][2] * inv1, acc[mi][ni][3] * inv1);
            } else {
                r0 = make_float2(acc[mi][ni][0] * alpha + b0, acc[mi][ni][1] * alpha + b1);
                r1 = make_float2(acc[mi][ni][2] * alpha + b0, acc[mi][ni][3] * alpha + b1);
            }
            if (outHalf) {
                *(uint32_t*)&Ch[(size_t)mrow * N + nc]       = h2pack(r0.x, r0.y);
                *(uint32_t*)&Ch[(size_t)(mrow + 8) * N + nc] = h2pack(r1.x, r1.y);
            } else {
                *(float2*)&Cf[(size_t)mrow * N + nc]       = r0;
                *(float2*)&Cf[(size_t)(mrow + 8) * N + nc] = r1;
            }
        }
    }
}

// ---------------- aux kernels ----------------------------------------------

// fp32 -> fp16 copy (prepares x for the projection GEMMs)
__global__ __launch_bounds__(256)
void half_copy4(const float4* __restrict__ in, uint2* __restrict__ out, int n4)
{
    int i = blockIdx.x * 256 + threadIdx.x;
    if (i < n4) {
        float4 v = in[i];
        uint2 o;
        o.x = h2pack(v.x, v.y);
        o.y = h2pack(v.z, v.w);
        out[i] = o;
    }
}

// out[C,R] = half(in[R,C]^T); R,C multiples of 32
__global__ __launch_bounds__(256)
void transpose32h(const float* __restrict__ in, __half* __restrict__ out, int R, int C)
{
    __shared__ float t[32][33];
    const int x  = blockIdx.x * 32 + threadIdx.x;
    const int y0 = blockIdx.y * 32;
#pragma unroll
    for (int j = threadIdx.y; j < 32; j += 8)
        t[j][threadIdx.x] = in[(size_t)(y0 + j) * C + x];
    __syncthreads();
    const int ox  = y0 + threadIdx.x;
    const int oy0 = blockIdx.x * 32;
#pragma unroll
    for (int j = threadIdx.y; j < 32; j += 8)
        out[(size_t)(oy0 + j) * R + ox] = __float2half_rn(t[threadIdx.x][j]);
}

// inv[r] = 1 / sum(partial[r][0..63])
__global__ __launch_bounds__(256)
void rowsum_inv(const float* __restrict__ partial, float* __restrict__ inv, int rows)
{
    int r = blockIdx.x * 256 + threadIdx.x;
    if (r < rows) {
        const float4* p = (const float4*)(partial + (size_t)r * 64);
        float s = 0.f;
#pragma unroll
        for (int i = 0; i < 16; i++) {
            float4 v = p[i];
            s += (v.x + v.y) + (v.z + v.w);
        }
        inv[r] = 1.0f / s;
    }
}

// ---------------- launch ----------------------------------------------------
extern "C" void kernel_launch(void* const* d_in, const int* in_sizes, int n_in,
                              void* d_out, int out_size)
{
    const float* x  = (const float*)d_in[0];
    const float* Wq = (const float*)d_in[1];
    const float* bq = (const float*)d_in[2];
    const float* Wk = (const float*)d_in[3];
    const float* bk = (const float*)d_in[4];
    const float* Wv = (const float*)d_in[5];
    const float* bv = (const float*)d_in[6];
    const float* Wo = (const float*)d_in[7];
    const float* bo = (const float*)d_in[8];
    float* out = (float*)d_out;

    __half *X, *Q, *K, *Vt, *P, *C, *Wt;
    float *PS, *INV;
    cudaGetSymbolAddress((void**)&X,   g_X);
    cudaGetSymbolAddress((void**)&Q,   g_Q);
    cudaGetSymbolAddress((void**)&K,   g_K);
    cudaGetSymbolAddress((void**)&Vt,  g_Vt);
    cudaGetSymbolAddress((void**)&P,   g_P);
    cudaGetSymbolAddress((void**)&C,   g_C);
    cudaGetSymbolAddress((void**)&Wt,  g_Wt);
    cudaGetSymbolAddress((void**)&PS,  g_ps);
    cudaGetSymbolAddress((void**)&INV, g_inv);

    cudaFuncSetAttribute(gemm_nt_mma, cudaFuncAttributeMaxDynamicSharedMemorySize, GEMM_SMEM);

    const float scale = 1.0f / 32.0f;   // 1/sqrt(1024)
    dim3 tb(32, 8);
    dim3 gT(DIM / 32, DIM / 32, 1);

    // 1) fp16 x
    half_copy4<<<(MTOT * DIM / 4 + 255) / 256, 256>>>((const float4*)x, (uint2*)X, MTOT * DIM / 4);

    // 2) transpose weights to [N,K] K-major fp16
    transpose32h<<<gT, tb>>>(Wq, Wt + 0 * (size_t)DIM * DIM, DIM, DIM);
    transpose32h<<<gT, tb>>>(Wk, Wt + 1 * (size_t)DIM * DIM, DIM, DIM);
    transpose32h<<<gT, tb>>>(Wv, Wt + 2 * (size_t)DIM * DIM, DIM, DIM);
    transpose32h<<<gT, tb>>>(Wo, Wt + 3 * (size_t)DIM * DIM, DIM, DIM);

    dim3 g_proj(DIM / BN, MTOT / BM, 1);     // 8 x 64
    dim3 g_sc(SEQ / BN, SEQ / BM, NB);       // 16 x 16 x 4
    dim3 g_ctx(DIM / BN, SEQ / BM, NB);      // 8 x 16 x 4

    // 3) Q/K projections (half out); V projection writes Vt transposed (half)
    gemm_nt_mma<<<g_proj, 256, GEMM_SMEM>>>(X, Wt + 0 * (size_t)DIM * DIM, bq, Q,
                                            DIM, DIM, 1.f, MODE_PLAIN, 1, nullptr, 0, 0, 0);
    gemm_nt_mma<<<g_proj, 256, GEMM_SMEM>>>(X, Wt + 1 * (size_t)DIM * DIM, bk, K,
                                            DIM, DIM, 1.f, MODE_PLAIN, 1, nullptr, 0, 0, 0);
    gemm_nt_mma<<<g_proj, 256, GEMM_SMEM>>>(X, Wt + 2 * (size_t)DIM * DIM, bv, Vt,
                                            DIM, DIM, 1.f, MODE_TRANSV, 1, nullptr, 0, 0, 0);

    // 4) expP = exp(scale * Q K^T) (half), partial row sums
    gemm_nt_mma<<<g_sc, 256, GEMM_SMEM>>>(Q, K, nullptr, P, SEQ, DIM, scale,
                                          MODE_EXP, 1, PS,
                                          (size_t)SEQ * DIM, (size_t)SEQ * DIM, (size_t)SEQ * SEQ);

    // 5) inv row sums
    rowsum_inv<<<MTOT / 256, 256>>>(PS, INV, MTOT);

    // 6) ctx = (expP * V) * inv   (A=P [S,S], B=Vt [D,S]) -> half
    gemm_nt_mma<<<g_ctx, 256, GEMM_SMEM>>>(P, Vt, nullptr, C, DIM, SEQ, 1.f,
                                           MODE_NORM, 1, INV,
                                           (size_t)SEQ * SEQ, (size_t)SEQ * DIM, (size_t)SEQ * DIM);

    // 7) out = ctx * Wo + bo (fp32 out)
    gemm_nt_mma<<<g_proj, 256, GEMM_SMEM>>>(C, Wt + 3 * (size_t)DIM * DIM, bo, out,
                                            DIM, DIM, 1.f, MODE_PLAIN, 0, nullptr, 0, 0, 0);
}